// round 1
// baseline (speedup 1.0000x reference)
#include <cuda_runtime.h>
#include <math.h>

#define T 1024
#define DIM 512
#define ED 1024
#define HID 256
#define NE 8
#define NM 325
#define TOPK 2
#define TOPM 8
#define ECAP 2048
#define MCAP 8192

// ---------------- scratch (device globals; no allocation) ----------------
__device__ float g_eo[T * DIM];                // combined expert output
__device__ float g_eo_slot[2][T * DIM];        // per-slot expert outputs (deterministic, no atomics)
__device__ float g_mo_slot[TOPM][T * DIM];     // per-slot micro outputs
__device__ int   g_ecount[NE];
__device__ int   g_elist[NE * ECAP];           // token | slot<<16
__device__ float g_ewt[NE * ECAP];
__device__ int   g_mcount[NM];
__device__ int   g_mlist[NM * MCAP];           // token | slot<<16
__device__ float g_mwt[NM * MCAP];

__device__ __forceinline__ float gelu_f(float x) {
    return 0.5f * x * (1.0f + erff(x * 0.70710678118654752f));
}
__device__ __forceinline__ float dot4(float4 a, float4 b) {
    return a.x * b.x + a.y * b.y + a.z * b.z + a.w * b.w;
}

// ---------------- K0: zero routing counters ----------------
__global__ void k_zero() {
    int t = threadIdx.x;
    if (t < NE) g_ecount[t] = 0;
    if (t < NM) g_mcount[t] = 0;
}

// ---------------- K1: expert router (top-2 of 8) + scatter ----------------
__global__ __launch_bounds__(256) void k_erouter(const float* __restrict__ x,
                                                 const float* __restrict__ rw,
                                                 const float* __restrict__ rb) {
    int t = blockIdx.x * blockDim.x + threadIdx.x;
    if (t >= T) return;
    const float4* xr = (const float4*)(x + (size_t)t * DIM);
    float lg[NE];
#pragma unroll
    for (int e = 0; e < NE; e++) lg[e] = __ldg(rb + e);
    for (int q = 0; q < DIM / 4; q++) {
        float4 xv = __ldg(xr + q);
#pragma unroll
        for (int e = 0; e < NE; e++) {
            float4 wv = __ldg((const float4*)(rw + (size_t)e * DIM) + q);
            lg[e] += dot4(wv, xv);
        }
    }
    // top-2 (ties -> lower index first, matching top_k)
    int a = 0;
#pragma unroll
    for (int e = 1; e < NE; e++) if (lg[e] > lg[a]) a = e;
    int b = (a == 0) ? 1 : 0;
#pragma unroll
    for (int e = 0; e < NE; e++) if (e != a && lg[e] > lg[b]) b = e;
    // softmax over all 8
    float m = lg[a];
    float s = 0.f;
#pragma unroll
    for (int e = 0; e < NE; e++) s += expf(lg[e] - m);
    float pa = expf(lg[a] - m) / s;
    float pb = expf(lg[b] - m) / s;
    float den = pa + pb + 1e-8f;
    float w0 = pa / den, w1 = pb / den;

    int p0 = atomicAdd(&g_ecount[a], 1);
    g_elist[a * ECAP + p0] = t;              // slot 0
    g_ewt[a * ECAP + p0] = w0;
    int p1 = atomicAdd(&g_ecount[b], 1);
    g_mlist[0] = g_mlist[0];                 // no-op (keep compiler honest)
    g_elist[b * ECAP + p1] = t | (1 << 16);  // slot 1
    g_ewt[b * ECAP + p1] = w1;
}

// ---------------- K2: grouped expert FFN (chunk of 16 tokens) ----------------
// smem: xs[16][512] + hs[16][1024] = 96KB dynamic
__global__ __launch_bounds__(256, 2) void k_effn(const float* __restrict__ x,
                                                 const float* __restrict__ w1,
                                                 const float* __restrict__ b1,
                                                 const float* __restrict__ w2,
                                                 const float* __restrict__ b2) {
    extern __shared__ float sm[];
    float* xs = sm;              // 16*512
    float* hs = sm + 16 * DIM;   // 16*1024
    __shared__ int stok[16];
    __shared__ int sslot[16];
    __shared__ float swt[16];

    int e = blockIdx.x;
    int cnt = g_ecount[e];
    int tid = threadIdx.x;
    const float* w1e = w1 + (size_t)e * ED * DIM;
    const float* w2e = w2 + (size_t)e * DIM * ED;

    for (int chunk = blockIdx.y; chunk * 16 < cnt; chunk += gridDim.y) {
        int base = chunk * 16;
        int n = min(16, cnt - base);
        __syncthreads();
        if (tid < 16) {
            if (tid < n) {
                int pk = g_elist[e * ECAP + base + tid];
                stok[tid] = pk & 0xffff;
                sslot[tid] = pk >> 16;
                swt[tid] = g_ewt[e * ECAP + base + tid];
            } else stok[tid] = -1;
        }
        __syncthreads();
        // load x tile
        for (int idx = tid; idx < 16 * (DIM / 4); idx += 256) {
            int c = idx >> 7, q = idx & 127;
            float4 v = (c < n) ? __ldg((const float4*)(x + (size_t)stok[c] * DIM) + q)
                               : make_float4(0.f, 0.f, 0.f, 0.f);
            ((float4*)xs)[idx] = v;
        }
        __syncthreads();
        // stage 1: hm[16][1024] = gelu(x @ w1^T + b1). thread owns 4 hidden units.
        float acc[4][16];
#pragma unroll
        for (int j = 0; j < 4; j++)
#pragma unroll
            for (int c = 0; c < 16; c++) acc[j][c] = 0.f;
        for (int k = 0; k < DIM; k += 4) {
            float4 wv[4];
#pragma unroll
            for (int j = 0; j < 4; j++)
                wv[j] = __ldg((const float4*)(w1e + (size_t)(tid + j * 256) * DIM + k));
            int kq = k >> 2;
#pragma unroll
            for (int c = 0; c < 16; c++) {
                float4 xv = ((float4*)xs)[c * 128 + kq];
#pragma unroll
                for (int j = 0; j < 4; j++) acc[j][c] += dot4(wv[j], xv);
            }
        }
#pragma unroll
        for (int j = 0; j < 4; j++) {
            int h = tid + j * 256;
            float bb = __ldg(b1 + (size_t)e * ED + h);
#pragma unroll
            for (int c = 0; c < 16; c++) hs[c * ED + h] = gelu_f(acc[j][c] + bb);
        }
        __syncthreads();
        // stage 2: y[16][512] = hm @ w2^T + b2; thread: 4 d's x 8 tokens
        int tg = tid >> 7, dth = tid & 127;
        float acc2[4][8];
#pragma unroll
        for (int j = 0; j < 4; j++)
#pragma unroll
            for (int c = 0; c < 8; c++) acc2[j][c] = 0.f;
        for (int h = 0; h < ED; h += 4) {
            float4 wv[4];
#pragma unroll
            for (int j = 0; j < 4; j++)
                wv[j] = __ldg((const float4*)(w2e + (size_t)(dth + j * 128) * ED + h));
            int hq = h >> 2;
#pragma unroll
            for (int c = 0; c < 8; c++) {
                float4 hv = ((float4*)hs)[(tg * 8 + c) * 256 + hq];
#pragma unroll
                for (int j = 0; j < 4; j++) acc2[j][c] += dot4(wv[j], hv);
            }
        }
#pragma unroll
        for (int c = 0; c < 8; c++) {
            int cc = tg * 8 + c;
            if (cc < n) {
                int t = stok[cc];
                float wt = swt[cc];
                float* dst = g_eo_slot[sslot[cc]] + (size_t)t * DIM;
#pragma unroll
                for (int j = 0; j < 4; j++) {
                    int d = dth + j * 128;
                    dst[d] = wt * (acc2[j][c] + __ldg(b2 + (size_t)e * DIM + d));
                }
            }
        }
    }
}

// ---------------- K3: micro router (top-8 of 325), also materializes eo ----------------
__global__ __launch_bounds__(256) void k_mrouter(const float* __restrict__ mw,
                                                 const float* __restrict__ mb) {
    __shared__ float xs[8 * DIM];           // 16KB
    __shared__ float probs[8][NM + 3];      // ~10.5KB
    int t0 = blockIdx.x * 8;
    int tid = threadIdx.x;
    // load eo = slot0 + slot1, also write to g_eo
    for (int idx = tid; idx < 8 * (DIM / 4); idx += 256) {
        int c = idx >> 7, q = idx & 127;
        int t = t0 + c;
        float4 a = ((const float4*)g_eo_slot[0])[t * 128 + q];
        float4 b = ((const float4*)g_eo_slot[1])[t * 128 + q];
        float4 v = make_float4(a.x + b.x, a.y + b.y, a.z + b.z, a.w + b.w);
        ((float4*)xs)[idx] = v;
        ((float4*)g_eo)[t * 128 + q] = v;
    }
    __syncthreads();
    // logits
    for (int m = tid; m < NM; m += 256) {
        float acc[8];
        float bb = __ldg(mb + m);
#pragma unroll
        for (int c = 0; c < 8; c++) acc[c] = bb;
        const float4* wr = (const float4*)(mw + (size_t)m * DIM);
        for (int q = 0; q < DIM / 4; q++) {
            float4 wv = __ldg(wr + q);
#pragma unroll
            for (int c = 0; c < 8; c++) acc[c] += dot4(wv, ((float4*)xs)[c * 128 + q]);
        }
#pragma unroll
        for (int c = 0; c < 8; c++) probs[c][m] = acc[c];
    }
    __syncthreads();
    // per-token softmax + top-8: warp w handles token w
    int w = tid >> 5, lane = tid & 31;
    float* pr = probs[w];
    float mx = -1e30f;
    for (int i = lane; i < NM; i += 32) mx = fmaxf(mx, pr[i]);
#pragma unroll
    for (int off = 16; off; off >>= 1) mx = fmaxf(mx, __shfl_xor_sync(0xffffffff, mx, off));
    float s = 0.f;
    for (int i = lane; i < NM; i += 32) {
        float p = expf(pr[i] - mx);
        pr[i] = p;
        s += p;
    }
#pragma unroll
    for (int off = 16; off; off >>= 1) s += __shfl_xor_sync(0xffffffff, s, off);
    __syncwarp();
    float vals[TOPM];
    int idxs[TOPM];
#pragma unroll
    for (int k = 0; k < TOPM; k++) {
        float bv = -1e30f;
        int bi = NM;
        for (int i = lane; i < NM; i += 32) {
            float v = pr[i];
            if (v > bv) { bv = v; bi = i; }
        }
#pragma unroll
        for (int off = 16; off; off >>= 1) {
            float ov = __shfl_down_sync(0xffffffff, bv, off);
            int oi = __shfl_down_sync(0xffffffff, bi, off);
            if (ov > bv || (ov == bv && oi < bi)) { bv = ov; bi = oi; }
        }
        bi = __shfl_sync(0xffffffff, bi, 0);
        bv = __shfl_sync(0xffffffff, bv, 0);
        vals[k] = bv;
        idxs[k] = bi;
        if (lane == 0) pr[bi] = -1e30f;
        __syncwarp();
    }
    if (lane == 0) {
        float ssum = 0.f;
#pragma unroll
        for (int k = 0; k < TOPM; k++) ssum += vals[k] / s;
        float den = ssum + 1e-8f;
        int t = t0 + w;
#pragma unroll
        for (int k = 0; k < TOPM; k++) {
            int m = idxs[k];
            float p = (vals[k] / s) / den;
            int pos = atomicAdd(&g_mcount[m], 1);
            g_mlist[m * MCAP + pos] = t | (k << 16);
            g_mwt[m * MCAP + pos] = p;
        }
    }
}

// ---------------- K4: grouped micro FFN + fused layernorm ----------------
// smem: xs[16][512] + hs[16][256] + rs[16][512] = 80KB dynamic
__global__ __launch_bounds__(256, 2) void k_mffn(const float* __restrict__ w1,
                                                 const float* __restrict__ b1,
                                                 const float* __restrict__ w2,
                                                 const float* __restrict__ b2,
                                                 const float* __restrict__ gg,
                                                 const float* __restrict__ bbeta) {
    extern __shared__ float sm[];
    float* xs = sm;                          // 16*512
    float* hs = sm + 16 * DIM;               // 16*256
    float* rs = sm + 16 * DIM + 16 * HID;    // 16*512
    __shared__ int stok[16];
    __shared__ int sslot[16];
    __shared__ float swt[16];

    int e = blockIdx.x;
    int cnt = g_mcount[e];
    int tid = threadIdx.x;
    const float* w1e = w1 + (size_t)e * HID * DIM;
    const float* w2e = w2 + (size_t)e * DIM * HID;

    for (int chunk = blockIdx.y; chunk * 16 < cnt; chunk += gridDim.y) {
        int base = chunk * 16;
        int n = min(16, cnt - base);
        __syncthreads();
        if (tid < 16) {
            if (tid < n) {
                int pk = g_mlist[e * MCAP + base + tid];
                stok[tid] = pk & 0xffff;
                sslot[tid] = pk >> 16;
                swt[tid] = g_mwt[e * MCAP + base + tid];
            } else stok[tid] = -1;
        }
        __syncthreads();
        for (int idx = tid; idx < 16 * (DIM / 4); idx += 256) {
            int c = idx >> 7, q = idx & 127;
            float4 v = (c < n) ? ((const float4*)g_eo)[stok[c] * 128 + q]
                               : make_float4(0.f, 0.f, 0.f, 0.f);
            ((float4*)xs)[idx] = v;
        }
        __syncthreads();
        // stage 1: hm[16][256]; thread: 4 hidden (hth + j*64) x 4 tokens (tg1*4..)
        int tg1 = tid >> 6, hth = tid & 63;
        float acc[4][4];
#pragma unroll
        for (int j = 0; j < 4; j++)
#pragma unroll
            for (int c = 0; c < 4; c++) acc[j][c] = 0.f;
        for (int k = 0; k < DIM; k += 4) {
            float4 wv[4];
#pragma unroll
            for (int j = 0; j < 4; j++)
                wv[j] = __ldg((const float4*)(w1e + (size_t)(hth + j * 64) * DIM + k));
            int kq = k >> 2;
#pragma unroll
            for (int c = 0; c < 4; c++) {
                float4 xv = ((float4*)xs)[(tg1 * 4 + c) * 128 + kq];
#pragma unroll
                for (int j = 0; j < 4; j++) acc[j][c] += dot4(wv[j], xv);
            }
        }
#pragma unroll
        for (int j = 0; j < 4; j++) {
            int h = hth + j * 64;
            float bb = __ldg(b1 + (size_t)e * HID + h);
#pragma unroll
            for (int c = 0; c < 4; c++) hs[(tg1 * 4 + c) * HID + h] = gelu_f(acc[j][c] + bb);
        }
        __syncthreads();
        // stage 2: ym[16][512]; thread: 4 d's x 8 tokens; then rs = eo + ym + b2
        int tg = tid >> 7, dth = tid & 127;
        float acc2[4][8];
#pragma unroll
        for (int j = 0; j < 4; j++)
#pragma unroll
            for (int c = 0; c < 8; c++) acc2[j][c] = 0.f;
        for (int h = 0; h < HID; h += 4) {
            float4 wv[4];
#pragma unroll
            for (int j = 0; j < 4; j++)
                wv[j] = __ldg((const float4*)(w2e + (size_t)(dth + j * 128) * HID + h));
            int hq = h >> 2;
#pragma unroll
            for (int c = 0; c < 8; c++) {
                float4 hv = ((float4*)hs)[(tg * 8 + c) * 64 + hq];
#pragma unroll
                for (int j = 0; j < 4; j++) acc2[j][c] += dot4(wv[j], hv);
            }
        }
#pragma unroll
        for (int c = 0; c < 8; c++) {
            int cc = tg * 8 + c;
#pragma unroll
            for (int j = 0; j < 4; j++) {
                int d = dth + j * 128;
                rs[cc * DIM + d] = xs[cc * DIM + d] + acc2[j][c] + __ldg(b2 + (size_t)e * DIM + d);
            }
        }
        __syncthreads();
        // layernorm per token + weighted write to mo_slot; warp w handles tokens 2w, 2w+1
        int w = tid >> 5, lane = tid & 31;
#pragma unroll
        for (int ci = 0; ci < 2; ci++) {
            int c = w * 2 + ci;
            if (c < n) {
                float s = 0.f, q = 0.f;
#pragma unroll
                for (int i = 0; i < 16; i++) {
                    float v = rs[c * DIM + lane + i * 32];
                    s += v;
                    q += v * v;
                }
#pragma unroll
                for (int off = 16; off; off >>= 1) {
                    s += __shfl_xor_sync(0xffffffff, s, off);
                    q += __shfl_xor_sync(0xffffffff, q, off);
                }
                float mu = s * (1.0f / DIM);
                float var = q * (1.0f / DIM) - mu * mu;
                float rstd = rsqrtf(var + 1e-5f);
                int t = stok[c];
                float p = swt[c];
                float* dst = g_mo_slot[sslot[c]] + (size_t)t * DIM;
#pragma unroll
                for (int i = 0; i < 16; i++) {
                    int d = lane + i * 32;
                    float nv = (rs[c * DIM + d] - mu) * rstd * __ldg(gg + (size_t)e * DIM + d)
                             + __ldg(bbeta + (size_t)e * DIM + d);
                    dst[d] = p * nv;
                }
            }
        }
    }
}

// ---------------- K5: combine + final layernorm ----------------
__global__ __launch_bounds__(256) void k_final(const float* __restrict__ ng,
                                               const float* __restrict__ nb,
                                               float* __restrict__ out) {
    int t = blockIdx.x;
    int tid = threadIdx.x;
    __shared__ float rsum[8], rsq[8];
    __shared__ float smu, srstd;
    float v[2];
#pragma unroll
    for (int j = 0; j < 2; j++) {
        int d = tid + j * 256;
        float c = g_eo[(size_t)t * DIM + d];
        float mo = 0.f;
#pragma unroll
        for (int k = 0; k < TOPM; k++) mo += g_mo_slot[k][(size_t)t * DIM + d];
        v[j] = c + 0.1f * mo;
    }
    float s = v[0] + v[1];
    float q = v[0] * v[0] + v[1] * v[1];
#pragma unroll
    for (int off = 16; off; off >>= 1) {
        s += __shfl_xor_sync(0xffffffff, s, off);
        q += __shfl_xor_sync(0xffffffff, q, off);
    }
    int w = tid >> 5, lane = tid & 31;
    if (lane == 0) { rsum[w] = s; rsq[w] = q; }
    __syncthreads();
    if (tid == 0) {
        float ts = 0.f, tq = 0.f;
#pragma unroll
        for (int i = 0; i < 8; i++) { ts += rsum[i]; tq += rsq[i]; }
        float mu = ts * (1.0f / DIM);
        float var = tq * (1.0f / DIM) - mu * mu;
        smu = mu;
        srstd = rsqrtf(var + 1e-5f);
    }
    __syncthreads();
    float mu = smu, rstd = srstd;
#pragma unroll
    for (int j = 0; j < 2; j++) {
        int d = tid + j * 256;
        out[(size_t)t * DIM + d] = (v[j] - mu) * rstd * __ldg(ng + d) + __ldg(nb + d);
    }
}

// ---------------- launch ----------------
extern "C" void kernel_launch(void* const* d_in, const int* in_sizes, int n_in,
                              void* d_out, int out_size) {
    const float* x    = (const float*)d_in[0];
    const float* rw   = (const float*)d_in[1];
    const float* rb   = (const float*)d_in[2];
    const float* ew1  = (const float*)d_in[3];
    const float* eb1  = (const float*)d_in[4];
    const float* ew2  = (const float*)d_in[5];
    const float* eb2  = (const float*)d_in[6];
    const float* mrw  = (const float*)d_in[7];
    const float* mrb  = (const float*)d_in[8];
    const float* mw1  = (const float*)d_in[9];
    const float* mb1  = (const float*)d_in[10];
    const float* mw2  = (const float*)d_in[11];
    const float* mb2  = (const float*)d_in[12];
    const float* mg   = (const float*)d_in[13];
    const float* mbt  = (const float*)d_in[14];
    const float* ng   = (const float*)d_in[15];
    const float* nb   = (const float*)d_in[16];
    float* out = (float*)d_out;

    cudaFuncSetAttribute(k_effn, cudaFuncAttributeMaxDynamicSharedMemorySize, 96 * 1024);
    cudaFuncSetAttribute(k_mffn, cudaFuncAttributeMaxDynamicSharedMemorySize, 80 * 1024);

    k_zero<<<1, 512>>>();
    k_erouter<<<T / 256, 256>>>(x, rw, rb);
    k_effn<<<dim3(NE, 32), 256, 96 * 1024>>>(x, ew1, eb1, ew2, eb2);
    k_mrouter<<<T / 8, 256>>>(mrw, mrb);
    k_mffn<<<dim3(NM, 2), 256, 80 * 1024>>>(mw1, mb1, mw2, mb2, mg, mbt);
    k_final<<<T, 256>>>(ng, nb, out);
}

// round 2
// speedup vs baseline: 1.1207x; 1.1207x over previous
#include <cuda_runtime.h>
#include <math.h>
#include <stdint.h>

#define T 1024
#define DIM 512
#define ED 1024
#define HID 256
#define NE 8
#define NM 325
#define TOPM 8
#define ECAP 2048
#define MCAP 8192
#define MT 16

// ---------------- scratch (device globals; no allocation) ----------------
__device__ float g_eo[T * DIM];
__device__ float g_eo_slot[2][T * DIM];
__device__ float g_mo_slot[TOPM][T * DIM];
__device__ int   g_ecount[NE];
__device__ int   g_elist[NE * ECAP];
__device__ float g_ewt[NE * ECAP];
__device__ int   g_mcount[NM];
__device__ int   g_mlist[NM * MCAP];
__device__ float g_mwt[NM * MCAP];

__device__ __forceinline__ float gelu_f(float x) {
    return 0.5f * x * (1.0f + erff(x * 0.70710678118654752f));
}
__device__ __forceinline__ float dot4(float4 a, float4 b) {
    return a.x * b.x + a.y * b.y + a.z * b.z + a.w * b.w;
}
__device__ __forceinline__ float tf32_rna(float x) {
    uint32_t u;
    asm("cvt.rna.tf32.f32 %0, %1;" : "=r"(u) : "f"(x));
    return __uint_as_float(u);
}
__device__ __forceinline__ void mma8(float* c, const uint32_t* a, const uint32_t* b) {
    asm volatile("mma.sync.aligned.m16n8k8.row.col.f32.tf32.tf32.f32 "
                 "{%0,%1,%2,%3}, {%4,%5,%6,%7}, {%8,%9}, {%0,%1,%2,%3};"
                 : "+f"(c[0]), "+f"(c[1]), "+f"(c[2]), "+f"(c[3])
                 : "r"(a[0]), "r"(a[1]), "r"(a[2]), "r"(a[3]), "r"(b[0]), "r"(b[1]));
}
__device__ __forceinline__ uint32_t fbits(float x) { return __float_as_uint(x); }

// ---------------- K0: zero routing counters ----------------
__global__ void k_zero() {
    int t = threadIdx.x;
    if (t < NE) g_ecount[t] = 0;
    if (t < NM) g_mcount[t] = 0;
}

// ---------------- K1: expert router (top-2 of 8, exact fp32) ----------------
__global__ __launch_bounds__(256) void k_erouter(const float* __restrict__ x,
                                                 const float* __restrict__ rw,
                                                 const float* __restrict__ rb) {
    int t = blockIdx.x * blockDim.x + threadIdx.x;
    if (t >= T) return;
    const float4* xr = (const float4*)(x + (size_t)t * DIM);
    float lg[NE];
#pragma unroll
    for (int e = 0; e < NE; e++) lg[e] = __ldg(rb + e);
    for (int q = 0; q < DIM / 4; q++) {
        float4 xv = __ldg(xr + q);
#pragma unroll
        for (int e = 0; e < NE; e++) {
            float4 wv = __ldg((const float4*)(rw + (size_t)e * DIM) + q);
            lg[e] += dot4(wv, xv);
        }
    }
    int a = 0;
#pragma unroll
    for (int e = 1; e < NE; e++) if (lg[e] > lg[a]) a = e;
    int b = (a == 0) ? 1 : 0;
#pragma unroll
    for (int e = 0; e < NE; e++) if (e != a && lg[e] > lg[b]) b = e;
    float m = lg[a];
    float s = 0.f;
#pragma unroll
    for (int e = 0; e < NE; e++) s += expf(lg[e] - m);
    float pa = expf(lg[a] - m) / s;
    float pb = expf(lg[b] - m) / s;
    float den = pa + pb + 1e-8f;
    int p0 = atomicAdd(&g_ecount[a], 1);
    g_elist[a * ECAP + p0] = t;
    g_ewt[a * ECAP + p0] = pa / den;
    int p1 = atomicAdd(&g_ecount[b], 1);
    g_elist[b * ECAP + p1] = t | (1 << 16);
    g_ewt[b * ECAP + p1] = pb / den;
}

// ---------------- K2: grouped expert FFN, split-tf32 mma (3-mma emulation) ----------------
// smem float offsets
#define E_W   0        // Wh(4608)+Wl(4608)  /  W2h(6144)+W2l(6144)
#define E_WL  4608
#define E_W2L 6144
#define E_X   12288    // Xh 16*36
#define E_XL  12864
#define E_H   13440    // Hh 16*132
#define E_HL  15552
#define E_TOT 17664    // floats -> 70656 bytes

__global__ __launch_bounds__(256, 2) void k_effn(const float* __restrict__ x,
                                                 const float* __restrict__ w1,
                                                 const float* __restrict__ b1,
                                                 const float* __restrict__ w2,
                                                 const float* __restrict__ b2) {
    extern __shared__ float sm[];
    __shared__ int stok[MT];
    __shared__ int sslot[MT];
    __shared__ float swt[MT];
    int e = blockIdx.x;
    int cnt = g_ecount[e];
    int tid = threadIdx.x;
    int warp = tid >> 5, lane = tid & 31;
    int g = lane >> 2, tg = lane & 3;
    const float* w1e = w1 + (size_t)e * ED * DIM;
    const float* w2e = w2 + (size_t)e * DIM * ED;

    for (int chunk = blockIdx.y; chunk * MT < cnt; chunk += gridDim.y) {
        int base = chunk * MT;
        int n = min(MT, cnt - base);
        __syncthreads();
        if (tid < MT) {
            if (tid < n) {
                int pk = g_elist[e * ECAP + base + tid];
                stok[tid] = pk & 0xffff;
                sslot[tid] = pk >> 16;
                swt[tid] = g_ewt[e * ECAP + base + tid];
            } else stok[tid] = -1;
        }
        __syncthreads();

        float c2[8][4];
#pragma unroll
        for (int j = 0; j < 8; j++)
#pragma unroll
            for (int r = 0; r < 4; r++) c2[j][r] = 0.f;

        for (int pass = 0; pass < 8; pass++) {
            int hbase = pass * 128;
            float c1[2][4];
#pragma unroll
            for (int j = 0; j < 2; j++)
#pragma unroll
                for (int r = 0; r < 4; r++) c1[j][r] = 0.f;

            // ---- stage 1: H[16,128] += X[16,512] @ W1[128,512]^T ----
            for (int k0 = 0; k0 < DIM; k0 += 32) {
                __syncthreads();
                if (tid < 128) {
                    int row = tid >> 3, c4 = (tid & 7) * 4;
                    float4 v = make_float4(0.f, 0.f, 0.f, 0.f);
                    int tk = stok[row];
                    if (tk >= 0) v = __ldg((const float4*)(x + (size_t)tk * DIM + k0 + c4));
                    float* Xh = sm + E_X + row * 36 + c4;
                    float* Xl = sm + E_XL + row * 36 + c4;
                    float h0 = tf32_rna(v.x); Xh[0] = h0; Xl[0] = tf32_rna(v.x - h0);
                    float h1 = tf32_rna(v.y); Xh[1] = h1; Xl[1] = tf32_rna(v.y - h1);
                    float h2 = tf32_rna(v.z); Xh[2] = h2; Xl[2] = tf32_rna(v.z - h2);
                    float h3 = tf32_rna(v.w); Xh[3] = h3; Xl[3] = tf32_rna(v.w - h3);
                }
                {
                    int c4 = (tid & 7) * 4;
#pragma unroll
                    for (int i = 0; i < 4; i++) {
                        int row = (tid >> 3) + i * 32;
                        float4 v = __ldg((const float4*)(w1e + (size_t)(hbase + row) * DIM + k0 + c4));
                        float* Wh = sm + E_W + row * 36 + c4;
                        float* Wl = sm + E_WL + row * 36 + c4;
                        float h0 = tf32_rna(v.x); Wh[0] = h0; Wl[0] = tf32_rna(v.x - h0);
                        float h1 = tf32_rna(v.y); Wh[1] = h1; Wl[1] = tf32_rna(v.y - h1);
                        float h2 = tf32_rna(v.z); Wh[2] = h2; Wl[2] = tf32_rna(v.z - h2);
                        float h3 = tf32_rna(v.w); Wh[3] = h3; Wl[3] = tf32_rna(v.w - h3);
                    }
                }
                __syncthreads();
#pragma unroll
                for (int kk = 0; kk < 32; kk += 8) {
                    uint32_t Ah[4], Al[4];
                    Ah[0] = fbits(sm[E_X + g * 36 + kk + tg]);
                    Ah[1] = fbits(sm[E_X + (g + 8) * 36 + kk + tg]);
                    Ah[2] = fbits(sm[E_X + g * 36 + kk + tg + 4]);
                    Ah[3] = fbits(sm[E_X + (g + 8) * 36 + kk + tg + 4]);
                    Al[0] = fbits(sm[E_XL + g * 36 + kk + tg]);
                    Al[1] = fbits(sm[E_XL + (g + 8) * 36 + kk + tg]);
                    Al[2] = fbits(sm[E_XL + g * 36 + kk + tg + 4]);
                    Al[3] = fbits(sm[E_XL + (g + 8) * 36 + kk + tg + 4]);
#pragma unroll
                    for (int j = 0; j < 2; j++) {
                        int nrow = warp * 16 + j * 8 + g;
                        uint32_t Bh[2], Bl[2];
                        Bh[0] = fbits(sm[E_W + nrow * 36 + kk + tg]);
                        Bh[1] = fbits(sm[E_W + nrow * 36 + kk + tg + 4]);
                        Bl[0] = fbits(sm[E_WL + nrow * 36 + kk + tg]);
                        Bl[1] = fbits(sm[E_WL + nrow * 36 + kk + tg + 4]);
                        mma8(c1[j], Ah, Bh);
                        mma8(c1[j], Ah, Bl);
                        mma8(c1[j], Al, Bh);
                    }
                }
            }
            // stage1 epilogue: bias + gelu -> Hs (hi/lo split)
#pragma unroll
            for (int j = 0; j < 2; j++)
#pragma unroll
                for (int r = 0; r < 4; r++) {
                    int row = g + 8 * (r >> 1);
                    int col = warp * 16 + j * 8 + 2 * tg + (r & 1);
                    float v = c1[j][r] + __ldg(b1 + (size_t)e * ED + hbase + col);
                    float gl = gelu_f(v);
                    float hh = tf32_rna(gl);
                    sm[E_H + row * 132 + col] = hh;
                    sm[E_HL + row * 132 + col] = tf32_rna(gl - hh);
                }

            // ---- stage 2: Y[16,512] += H[16,128] @ W2[512, hbase:+128]^T ----
            for (int k2 = 0; k2 < 128; k2 += 8) {
                __syncthreads();
                {
                    int c4 = (tid & 1) * 4;
#pragma unroll
                    for (int i = 0; i < 4; i++) {
                        int row = (tid >> 1) + i * 128;
                        float4 v = __ldg((const float4*)(w2e + (size_t)row * ED + hbase + k2 + c4));
                        float* Wh = sm + E_W + row * 12 + c4;
                        float* Wl = sm + E_W2L + row * 12 + c4;
                        float h0 = tf32_rna(v.x); Wh[0] = h0; Wl[0] = tf32_rna(v.x - h0);
                        float h1 = tf32_rna(v.y); Wh[1] = h1; Wl[1] = tf32_rna(v.y - h1);
                        float h2 = tf32_rna(v.z); Wh[2] = h2; Wl[2] = tf32_rna(v.z - h2);
                        float h3 = tf32_rna(v.w); Wh[3] = h3; Wl[3] = tf32_rna(v.w - h3);
                    }
                }
                __syncthreads();
                uint32_t Ah[4], Al[4];
                Ah[0] = fbits(sm[E_H + g * 132 + k2 + tg]);
                Ah[1] = fbits(sm[E_H + (g + 8) * 132 + k2 + tg]);
                Ah[2] = fbits(sm[E_H + g * 132 + k2 + tg + 4]);
                Ah[3] = fbits(sm[E_H + (g + 8) * 132 + k2 + tg + 4]);
                Al[0] = fbits(sm[E_HL + g * 132 + k2 + tg]);
                Al[1] = fbits(sm[E_HL + (g + 8) * 132 + k2 + tg]);
                Al[2] = fbits(sm[E_HL + g * 132 + k2 + tg + 4]);
                Al[3] = fbits(sm[E_HL + (g + 8) * 132 + k2 + tg + 4]);
#pragma unroll
                for (int j = 0; j < 8; j++) {
                    int nrow = warp * 64 + j * 8 + g;
                    uint32_t Bh[2], Bl[2];
                    Bh[0] = fbits(sm[E_W + nrow * 12 + tg]);
                    Bh[1] = fbits(sm[E_W + nrow * 12 + tg + 4]);
                    Bl[0] = fbits(sm[E_W2L + nrow * 12 + tg]);
                    Bl[1] = fbits(sm[E_W2L + nrow * 12 + tg + 4]);
                    mma8(c2[j], Ah, Bh);
                    mma8(c2[j], Ah, Bl);
                    mma8(c2[j], Al, Bh);
                }
            }
        }
        // chunk epilogue: y = wt*(acc + b2) -> per-slot buffer
#pragma unroll
        for (int j = 0; j < 8; j++)
#pragma unroll
            for (int half = 0; half < 2; half++) {
                int row = g + 8 * half;
                if (row < n) {
                    int col = warp * 64 + j * 8 + 2 * tg;
                    int tk = stok[row];
                    float wt = swt[row];
                    float2 bb = __ldg((const float2*)(b2 + (size_t)e * DIM + col));
                    float2 o;
                    o.x = wt * (c2[j][half * 2 + 0] + bb.x);
                    o.y = wt * (c2[j][half * 2 + 1] + bb.y);
                    *(float2*)(g_eo_slot[sslot[row]] + (size_t)tk * DIM + col) = o;
                }
            }
    }
}

// ---------------- K3: micro router (top-8 of 325, exact fp32), materializes eo ----------------
__global__ __launch_bounds__(512) void k_mrouter(const float* __restrict__ mw,
                                                 const float* __restrict__ mb) {
    __shared__ float xs[8 * DIM];
    __shared__ float probs[8][NM + 3];
    int t0 = blockIdx.x * 8;
    int tid = threadIdx.x;
    for (int idx = tid; idx < 8 * (DIM / 4); idx += 512) {
        int c = idx >> 7, q = idx & 127;
        int t = t0 + c;
        float4 a = ((const float4*)g_eo_slot[0])[t * 128 + q];
        float4 b = ((const float4*)g_eo_slot[1])[t * 128 + q];
        float4 v = make_float4(a.x + b.x, a.y + b.y, a.z + b.z, a.w + b.w);
        ((float4*)xs)[idx] = v;
        ((float4*)g_eo)[t * 128 + q] = v;
    }
    __syncthreads();
    for (int m = tid; m < NM; m += 512) {
        float acc[8];
        float bb = __ldg(mb + m);
#pragma unroll
        for (int c = 0; c < 8; c++) acc[c] = bb;
        const float4* wr = (const float4*)(mw + (size_t)m * DIM);
        for (int q = 0; q < DIM / 4; q++) {
            float4 wv = __ldg(wr + q);
#pragma unroll
            for (int c = 0; c < 8; c++) acc[c] += dot4(wv, ((float4*)xs)[c * 128 + q]);
        }
#pragma unroll
        for (int c = 0; c < 8; c++) probs[c][m] = acc[c];
    }
    __syncthreads();
    int w = tid >> 5, lane = tid & 31;
    if (w < 8) {
        float* pr = probs[w];
        float mx = -1e30f;
        for (int i = lane; i < NM; i += 32) mx = fmaxf(mx, pr[i]);
#pragma unroll
        for (int off = 16; off; off >>= 1) mx = fmaxf(mx, __shfl_xor_sync(0xffffffff, mx, off));
        float s = 0.f;
        for (int i = lane; i < NM; i += 32) {
            float p = expf(pr[i] - mx);
            pr[i] = p;
            s += p;
        }
#pragma unroll
        for (int off = 16; off; off >>= 1) s += __shfl_xor_sync(0xffffffff, s, off);
        __syncwarp();
        float vals[TOPM];
        int idxs[TOPM];
#pragma unroll
        for (int k = 0; k < TOPM; k++) {
            float bv = -1e30f;
            int bi = NM;
            for (int i = lane; i < NM; i += 32) {
                float v = pr[i];
                if (v > bv) { bv = v; bi = i; }
            }
#pragma unroll
            for (int off = 16; off; off >>= 1) {
                float ov = __shfl_down_sync(0xffffffff, bv, off);
                int oi = __shfl_down_sync(0xffffffff, bi, off);
                if (ov > bv || (ov == bv && oi < bi)) { bv = ov; bi = oi; }
            }
            bi = __shfl_sync(0xffffffff, bi, 0);
            bv = __shfl_sync(0xffffffff, bv, 0);
            vals[k] = bv;
            idxs[k] = bi;
            if (lane == 0) pr[bi] = -1e30f;
            __syncwarp();
        }
        if (lane == 0) {
            float ssum = 0.f;
#pragma unroll
            for (int k = 0; k < TOPM; k++) ssum += vals[k] / s;
            float den = ssum + 1e-8f;
            int t = t0 + w;
#pragma unroll
            for (int k = 0; k < TOPM; k++) {
                int m = idxs[k];
                float p = (vals[k] / s) / den;
                int pos = atomicAdd(&g_mcount[m], 1);
                g_mlist[m * MCAP + pos] = t | (k << 16);
                g_mwt[m * MCAP + pos] = p;
            }
        }
    }
}

// ---------------- K4: grouped micro FFN (single tf32 mma) + fused layernorm ----------------
#define M_W  0        // Ws 128*36=4608 / W2s 512*20=10240
#define M_X  10240    // 16*36
#define M_H  10816    // 16*132
#define M_TOT 12928   // floats -> 51712 bytes ; rs[16][516]=8256 overlays M_W

__global__ __launch_bounds__(256, 2) void k_mffn(const float* __restrict__ w1,
                                                 const float* __restrict__ b1,
                                                 const float* __restrict__ w2,
                                                 const float* __restrict__ b2,
                                                 const float* __restrict__ gg,
                                                 const float* __restrict__ bbeta) {
    extern __shared__ float sm[];
    __shared__ int stok[MT];
    __shared__ int sslot[MT];
    __shared__ float swt[MT];
    int e = blockIdx.x;
    int cnt = g_mcount[e];
    int tid = threadIdx.x;
    int warp = tid >> 5, lane = tid & 31;
    int g = lane >> 2, tg = lane & 3;
    const float* w1e = w1 + (size_t)e * HID * DIM;
    const float* w2e = w2 + (size_t)e * DIM * HID;

    for (int chunk = blockIdx.y; chunk * MT < cnt; chunk += gridDim.y) {
        int base = chunk * MT;
        int n = min(MT, cnt - base);
        __syncthreads();
        if (tid < MT) {
            if (tid < n) {
                int pk = g_mlist[e * MCAP + base + tid];
                stok[tid] = pk & 0xffff;
                sslot[tid] = pk >> 16;
                swt[tid] = g_mwt[e * MCAP + base + tid];
            } else stok[tid] = -1;
        }
        __syncthreads();

        float c2[8][4];
#pragma unroll
        for (int j = 0; j < 8; j++)
#pragma unroll
            for (int r = 0; r < 4; r++) c2[j][r] = 0.f;

        for (int pass = 0; pass < 2; pass++) {
            int hbase = pass * 128;
            float c1[2][4];
#pragma unroll
            for (int j = 0; j < 2; j++)
#pragma unroll
                for (int r = 0; r < 4; r++) c1[j][r] = 0.f;

            // stage 1: H[16,128] = eo[16,512] @ W1[hbase:+128, :]^T
            for (int k0 = 0; k0 < DIM; k0 += 32) {
                __syncthreads();
                if (tid < 128) {
                    int row = tid >> 3, c4 = (tid & 7) * 4;
                    float4 v = make_float4(0.f, 0.f, 0.f, 0.f);
                    int tk = stok[row];
                    if (tk >= 0) v = ((const float4*)g_eo)[tk * 128 + (k0 + c4) / 4];
                    float* X = sm + M_X + row * 36 + c4;
                    X[0] = tf32_rna(v.x); X[1] = tf32_rna(v.y);
                    X[2] = tf32_rna(v.z); X[3] = tf32_rna(v.w);
                }
                {
                    int c4 = (tid & 7) * 4;
#pragma unroll
                    for (int i = 0; i < 4; i++) {
                        int row = (tid >> 3) + i * 32;
                        float4 v = __ldg((const float4*)(w1e + (size_t)(hbase + row) * DIM + k0 + c4));
                        float* W = sm + M_W + row * 36 + c4;
                        W[0] = tf32_rna(v.x); W[1] = tf32_rna(v.y);
                        W[2] = tf32_rna(v.z); W[3] = tf32_rna(v.w);
                    }
                }
                __syncthreads();
#pragma unroll
                for (int kk = 0; kk < 32; kk += 8) {
                    uint32_t A[4];
                    A[0] = fbits(sm[M_X + g * 36 + kk + tg]);
                    A[1] = fbits(sm[M_X + (g + 8) * 36 + kk + tg]);
                    A[2] = fbits(sm[M_X + g * 36 + kk + tg + 4]);
                    A[3] = fbits(sm[M_X + (g + 8) * 36 + kk + tg + 4]);
#pragma unroll
                    for (int j = 0; j < 2; j++) {
                        int nrow = warp * 16 + j * 8 + g;
                        uint32_t B[2];
                        B[0] = fbits(sm[M_W + nrow * 36 + kk + tg]);
                        B[1] = fbits(sm[M_W + nrow * 36 + kk + tg + 4]);
                        mma8(c1[j], A, B);
                    }
                }
            }
#pragma unroll
            for (int j = 0; j < 2; j++)
#pragma unroll
                for (int r = 0; r < 4; r++) {
                    int row = g + 8 * (r >> 1);
                    int col = warp * 16 + j * 8 + 2 * tg + (r & 1);
                    float v = c1[j][r] + __ldg(b1 + (size_t)e * HID + hbase + col);
                    sm[M_H + row * 132 + col] = tf32_rna(gelu_f(v));
                }

            // stage 2: Y[16,512] += H[16,128] @ W2[:, hbase:+128]^T
            for (int k2 = 0; k2 < 128; k2 += 16) {
                __syncthreads();
                {
                    int c4 = (tid & 3) * 4;
#pragma unroll
                    for (int i = 0; i < 8; i++) {
                        int row = (tid >> 2) + i * 64;
                        float4 v = __ldg((const float4*)(w2e + (size_t)row * HID + hbase + k2 + c4));
                        float* W = sm + M_W + row * 20 + c4;
                        W[0] = tf32_rna(v.x); W[1] = tf32_rna(v.y);
                        W[2] = tf32_rna(v.z); W[3] = tf32_rna(v.w);
                    }
                }
                __syncthreads();
#pragma unroll
                for (int kk = 0; kk < 16; kk += 8) {
                    uint32_t A[4];
                    A[0] = fbits(sm[M_H + g * 132 + k2 + kk + tg]);
                    A[1] = fbits(sm[M_H + (g + 8) * 132 + k2 + kk + tg]);
                    A[2] = fbits(sm[M_H + g * 132 + k2 + kk + tg + 4]);
                    A[3] = fbits(sm[M_H + (g + 8) * 132 + k2 + kk + tg + 4]);
#pragma unroll
                    for (int j = 0; j < 8; j++) {
                        int nrow = warp * 64 + j * 8 + g;
                        uint32_t B[2];
                        B[0] = fbits(sm[M_W + nrow * 20 + kk + tg]);
                        B[1] = fbits(sm[M_W + nrow * 20 + kk + tg + 4]);
                        mma8(c2[j], A, B);
                    }
                }
            }
        }
        // epilogue: rs = eo + ym + b2 (smem), then per-token layernorm
        __syncthreads();
        float* rs = sm;  // 16 x 516, overlays weight staging
#pragma unroll
        for (int j = 0; j < 8; j++)
#pragma unroll
            for (int half = 0; half < 2; half++) {
                int row = g + 8 * half;
                if (row < n) {
                    int col = warp * 64 + j * 8 + 2 * tg;
                    int tk = stok[row];
                    float2 bb = __ldg((const float2*)(b2 + (size_t)e * DIM + col));
                    float2 ev = *(const float2*)(g_eo + (size_t)tk * DIM + col);
                    rs[row * 516 + col] = ev.x + c2[j][half * 2 + 0] + bb.x;
                    rs[row * 516 + col + 1] = ev.y + c2[j][half * 2 + 1] + bb.y;
                }
            }
        __syncthreads();
#pragma unroll
        for (int ci = 0; ci < 2; ci++) {
            int c = warp * 2 + ci;
            if (c < n) {
                float s = 0.f, q = 0.f;
#pragma unroll
                for (int i = 0; i < 16; i++) {
                    float v = rs[c * 516 + lane + i * 32];
                    s += v;
                    q += v * v;
                }
#pragma unroll
                for (int off = 16; off; off >>= 1) {
                    s += __shfl_xor_sync(0xffffffff, s, off);
                    q += __shfl_xor_sync(0xffffffff, q, off);
                }
                float mu = s * (1.0f / DIM);
                float var = q * (1.0f / DIM) - mu * mu;
                float rstd = rsqrtf(var + 1e-5f);
                int t = stok[c];
                float p = swt[c];
                float* dst = g_mo_slot[sslot[c]] + (size_t)t * DIM;
#pragma unroll
                for (int i = 0; i < 16; i++) {
                    int d = lane + i * 32;
                    float nv = (rs[c * 516 + d] - mu) * rstd * __ldg(gg + (size_t)e * DIM + d)
                             + __ldg(bbeta + (size_t)e * DIM + d);
                    dst[d] = p * nv;
                }
            }
        }
    }
}

// ---------------- K5: combine + final layernorm ----------------
__global__ __launch_bounds__(256) void k_final(const float* __restrict__ ng,
                                               const float* __restrict__ nb,
                                               float* __restrict__ out) {
    int t = blockIdx.x;
    int tid = threadIdx.x;
    __shared__ float rsum[8], rsq[8];
    __shared__ float smu, srstd;
    float v[2];
#pragma unroll
    for (int j = 0; j < 2; j++) {
        int d = tid + j * 256;
        float c = g_eo[(size_t)t * DIM + d];
        float mo = 0.f;
#pragma unroll
        for (int k = 0; k < TOPM; k++) mo += g_mo_slot[k][(size_t)t * DIM + d];
        v[j] = c + 0.1f * mo;
    }
    float s = v[0] + v[1];
    float q = v[0] * v[0] + v[1] * v[1];
#pragma unroll
    for (int off = 16; off; off >>= 1) {
        s += __shfl_xor_sync(0xffffffff, s, off);
        q += __shfl_xor_sync(0xffffffff, q, off);
    }
    int w = tid >> 5, lane = tid & 31;
    if (lane == 0) { rsum[w] = s; rsq[w] = q; }
    __syncthreads();
    if (tid == 0) {
        float ts = 0.f, tq = 0.f;
#pragma unroll
        for (int i = 0; i < 8; i++) { ts += rsum[i]; tq += rsq[i]; }
        float mu = ts * (1.0f / DIM);
        float var = tq * (1.0f / DIM) - mu * mu;
        smu = mu;
        srstd = rsqrtf(var + 1e-5f);
    }
    __syncthreads();
    float mu = smu, rstd = srstd;
#pragma unroll
    for (int j = 0; j < 2; j++) {
        int d = tid + j * 256;
        out[(size_t)t * DIM + d] = (v[j] - mu) * rstd * __ldg(ng + d) + __ldg(nb + d);
    }
}

// ---------------- launch ----------------
extern "C" void kernel_launch(void* const* d_in, const int* in_sizes, int n_in,
                              void* d_out, int out_size) {
    const float* x   = (const float*)d_in[0];
    const float* rw  = (const float*)d_in[1];
    const float* rb  = (const float*)d_in[2];
    const float* ew1 = (const float*)d_in[3];
    const float* eb1 = (const float*)d_in[4];
    const float* ew2 = (const float*)d_in[5];
    const float* eb2 = (const float*)d_in[6];
    const float* mrw = (const float*)d_in[7];
    const float* mrb = (const float*)d_in[8];
    const float* mw1 = (const float*)d_in[9];
    const float* mb1 = (const float*)d_in[10];
    const float* mw2 = (const float*)d_in[11];
    const float* mb2 = (const float*)d_in[12];
    const float* mg  = (const float*)d_in[13];
    const float* mbt = (const float*)d_in[14];
    const float* ng  = (const float*)d_in[15];
    const float* nb  = (const float*)d_in[16];
    float* out = (float*)d_out;

    cudaFuncSetAttribute(k_effn, cudaFuncAttributeMaxDynamicSharedMemorySize, E_TOT * 4);
    cudaFuncSetAttribute(k_mffn, cudaFuncAttributeMaxDynamicSharedMemorySize, M_TOT * 4);

    k_zero<<<1, 512>>>();
    k_erouter<<<T / 256, 256>>>(x, rw, rb);
    k_effn<<<dim3(NE, 16), 256, E_TOT * 4>>>(x, ew1, eb1, ew2, eb2);
    k_mrouter<<<T / 8, 512>>>(mrw, mrb);
    k_mffn<<<dim3(NM, 2), 256, M_TOT * 4>>>(mw1, mb1, mw2, mb2, mg, mbt);
    k_final<<<T, 256>>>(ng, nb, out);
}

// round 3
// speedup vs baseline: 1.1316x; 1.0097x over previous
#include <cuda_runtime.h>
#include <math.h>
#include <stdint.h>

#define T 1024
#define DIM 512
#define ED 1024
#define HID 256
#define NE 8
#define NM 325
#define TOPM 8
#define ECAP 2048
#define MCAP 8192
#define MT 16

// ---------------- scratch (device globals; no allocation) ----------------
__device__ float g_eo[T * DIM];
__device__ float g_eo_slot[2][T * DIM];
__device__ float g_mo_slot[TOPM][T * DIM];
__device__ int   g_ecount[NE];
__device__ int   g_elist[NE * ECAP];
__device__ float g_ewt[NE * ECAP];
__device__ int   g_mcount[NM];
__device__ int   g_mlist[NM * MCAP];
__device__ float g_mwt[NM * MCAP];

__device__ __forceinline__ float gelu_f(float x) {
    return 0.5f * x * (1.0f + erff(x * 0.70710678118654752f));
}
__device__ __forceinline__ float dot4(float4 a, float4 b) {
    return a.x * b.x + a.y * b.y + a.z * b.z + a.w * b.w;
}
__device__ __forceinline__ float tf32_rna(float x) {
    uint32_t u;
    asm("cvt.rna.tf32.f32 %0, %1;" : "=r"(u) : "f"(x));
    return __uint_as_float(u);
}
__device__ __forceinline__ void mma8(float* c, const uint32_t* a, const uint32_t* b) {
    asm volatile("mma.sync.aligned.m16n8k8.row.col.f32.tf32.tf32.f32 "
                 "{%0,%1,%2,%3}, {%4,%5,%6,%7}, {%8,%9}, {%0,%1,%2,%3};"
                 : "+f"(c[0]), "+f"(c[1]), "+f"(c[2]), "+f"(c[3])
                 : "r"(a[0]), "r"(a[1]), "r"(a[2]), "r"(a[3]), "r"(b[0]), "r"(b[1]));
}
__device__ __forceinline__ uint32_t fbits(float x) { return __float_as_uint(x); }

// ---------------- K0: zero routing counters ----------------
__global__ void k_zero() {
    int t = threadIdx.x;
    if (t < NE) g_ecount[t] = 0;
    if (t < NM) g_mcount[t] = 0;
}

// ---------------- K1: expert router (top-2 of 8, exact fp32) ----------------
__global__ __launch_bounds__(256) void k_erouter(const float* __restrict__ x,
                                                 const float* __restrict__ rw,
                                                 const float* __restrict__ rb) {
    int t = blockIdx.x * blockDim.x + threadIdx.x;
    if (t >= T) return;
    const float4* xr = (const float4*)(x + (size_t)t * DIM);
    float lg[NE];
#pragma unroll
    for (int e = 0; e < NE; e++) lg[e] = __ldg(rb + e);
    for (int q = 0; q < DIM / 4; q++) {
        float4 xv = __ldg(xr + q);
#pragma unroll
        for (int e = 0; e < NE; e++) {
            float4 wv = __ldg((const float4*)(rw + (size_t)e * DIM) + q);
            lg[e] += dot4(wv, xv);
        }
    }
    int a = 0;
#pragma unroll
    for (int e = 1; e < NE; e++) if (lg[e] > lg[a]) a = e;
    int b = (a == 0) ? 1 : 0;
#pragma unroll
    for (int e = 0; e < NE; e++) if (e != a && lg[e] > lg[b]) b = e;
    float m = lg[a];
    float s = 0.f;
#pragma unroll
    for (int e = 0; e < NE; e++) s += expf(lg[e] - m);
    float pa = expf(lg[a] - m) / s;
    float pb = expf(lg[b] - m) / s;
    float den = pa + pb + 1e-8f;
    int p0 = atomicAdd(&g_ecount[a], 1);
    g_elist[a * ECAP + p0] = t;
    g_ewt[a * ECAP + p0] = pa / den;
    int p1 = atomicAdd(&g_ecount[b], 1);
    g_elist[b * ECAP + p1] = t | (1 << 16);
    g_ewt[b * ECAP + p1] = pb / den;
}

// ---------------- K2: grouped expert FFN, split-tf32 mma (3-mma emulation) ----------------
// smem float offsets
#define E_W   0        // Wh(4608)+Wl(4608)  /  W2h(6144)+W2l(6144)
#define E_WL  4608
#define E_W2L 6144
#define E_X   12288    // Xh 16*36
#define E_XL  12864
#define E_H   13440    // Hh 16*132
#define E_HL  15552
#define E_TOT 17664    // floats -> 70656 bytes

__global__ __launch_bounds__(256, 2) void k_effn(const float* __restrict__ x,
                                                 const float* __restrict__ w1,
                                                 const float* __restrict__ b1,
                                                 const float* __restrict__ w2,
                                                 const float* __restrict__ b2) {
    extern __shared__ float sm[];
    __shared__ int stok[MT];
    __shared__ int sslot[MT];
    __shared__ float swt[MT];
    int e = blockIdx.x;
    int cnt = g_ecount[e];
    int tid = threadIdx.x;
    int warp = tid >> 5, lane = tid & 31;
    int g = lane >> 2, tg = lane & 3;
    const float* w1e = w1 + (size_t)e * ED * DIM;
    const float* w2e = w2 + (size_t)e * DIM * ED;

    for (int chunk = blockIdx.y; chunk * MT < cnt; chunk += gridDim.y) {
        int base = chunk * MT;
        int n = min(MT, cnt - base);
        __syncthreads();
        if (tid < MT) {
            if (tid < n) {
                int pk = g_elist[e * ECAP + base + tid];
                stok[tid] = pk & 0xffff;
                sslot[tid] = pk >> 16;
                swt[tid] = g_ewt[e * ECAP + base + tid];
            } else stok[tid] = -1;
        }
        __syncthreads();

        float c2[8][4];
#pragma unroll
        for (int j = 0; j < 8; j++)
#pragma unroll
            for (int r = 0; r < 4; r++) c2[j][r] = 0.f;

        for (int pass = 0; pass < 8; pass++) {
            int hbase = pass * 128;
            float c1[2][4];
#pragma unroll
            for (int j = 0; j < 2; j++)
#pragma unroll
                for (int r = 0; r < 4; r++) c1[j][r] = 0.f;

            // ---- stage 1: H[16,128] += X[16,512] @ W1[128,512]^T ----
            for (int k0 = 0; k0 < DIM; k0 += 32) {
                __syncthreads();
                if (tid < 128) {
                    int row = tid >> 3, c4 = (tid & 7) * 4;
                    float4 v = make_float4(0.f, 0.f, 0.f, 0.f);
                    int tk = stok[row];
                    if (tk >= 0) v = __ldg((const float4*)(x + (size_t)tk * DIM + k0 + c4));
                    float* Xh = sm + E_X + row * 36 + c4;
                    float* Xl = sm + E_XL + row * 36 + c4;
                    float h0 = tf32_rna(v.x); Xh[0] = h0; Xl[0] = tf32_rna(v.x - h0);
                    float h1 = tf32_rna(v.y); Xh[1] = h1; Xl[1] = tf32_rna(v.y - h1);
                    float h2 = tf32_rna(v.z); Xh[2] = h2; Xl[2] = tf32_rna(v.z - h2);
                    float h3 = tf32_rna(v.w); Xh[3] = h3; Xl[3] = tf32_rna(v.w - h3);
                }
                {
                    int c4 = (tid & 7) * 4;
#pragma unroll
                    for (int i = 0; i < 4; i++) {
                        int row = (tid >> 3) + i * 32;
                        float4 v = __ldg((const float4*)(w1e + (size_t)(hbase + row) * DIM + k0 + c4));
                        float* Wh = sm + E_W + row * 36 + c4;
                        float* Wl = sm + E_WL + row * 36 + c4;
                        float h0 = tf32_rna(v.x); Wh[0] = h0; Wl[0] = tf32_rna(v.x - h0);
                        float h1 = tf32_rna(v.y); Wh[1] = h1; Wl[1] = tf32_rna(v.y - h1);
                        float h2 = tf32_rna(v.z); Wh[2] = h2; Wl[2] = tf32_rna(v.z - h2);
                        float h3 = tf32_rna(v.w); Wh[3] = h3; Wl[3] = tf32_rna(v.w - h3);
                    }
                }
                __syncthreads();
#pragma unroll
                for (int kk = 0; kk < 32; kk += 8) {
                    uint32_t Ah[4], Al[4];
                    Ah[0] = fbits(sm[E_X + g * 36 + kk + tg]);
                    Ah[1] = fbits(sm[E_X + (g + 8) * 36 + kk + tg]);
                    Ah[2] = fbits(sm[E_X + g * 36 + kk + tg + 4]);
                    Ah[3] = fbits(sm[E_X + (g + 8) * 36 + kk + tg + 4]);
                    Al[0] = fbits(sm[E_XL + g * 36 + kk + tg]);
                    Al[1] = fbits(sm[E_XL + (g + 8) * 36 + kk + tg]);
                    Al[2] = fbits(sm[E_XL + g * 36 + kk + tg + 4]);
                    Al[3] = fbits(sm[E_XL + (g + 8) * 36 + kk + tg + 4]);
#pragma unroll
                    for (int j = 0; j < 2; j++) {
                        int nrow = warp * 16 + j * 8 + g;
                        uint32_t Bh[2], Bl[2];
                        Bh[0] = fbits(sm[E_W + nrow * 36 + kk + tg]);
                        Bh[1] = fbits(sm[E_W + nrow * 36 + kk + tg + 4]);
                        Bl[0] = fbits(sm[E_WL + nrow * 36 + kk + tg]);
                        Bl[1] = fbits(sm[E_WL + nrow * 36 + kk + tg + 4]);
                        mma8(c1[j], Ah, Bh);
                        mma8(c1[j], Ah, Bl);
                        mma8(c1[j], Al, Bh);
                    }
                }
            }
            // stage1 epilogue: bias + gelu -> Hs (hi/lo split)
#pragma unroll
            for (int j = 0; j < 2; j++)
#pragma unroll
                for (int r = 0; r < 4; r++) {
                    int row = g + 8 * (r >> 1);
                    int col = warp * 16 + j * 8 + 2 * tg + (r & 1);
                    float v = c1[j][r] + __ldg(b1 + (size_t)e * ED + hbase + col);
                    float gl = gelu_f(v);
                    float hh = tf32_rna(gl);
                    sm[E_H + row * 132 + col] = hh;
                    sm[E_HL + row * 132 + col] = tf32_rna(gl - hh);
                }

            // ---- stage 2: Y[16,512] += H[16,128] @ W2[512, hbase:+128]^T ----
            for (int k2 = 0; k2 < 128; k2 += 8) {
                __syncthreads();
                {
                    int c4 = (tid & 1) * 4;
#pragma unroll
                    for (int i = 0; i < 4; i++) {
                        int row = (tid >> 1) + i * 128;
                        float4 v = __ldg((const float4*)(w2e + (size_t)row * ED + hbase + k2 + c4));
                        float* Wh = sm + E_W + row * 12 + c4;
                        float* Wl = sm + E_W2L + row * 12 + c4;
                        float h0 = tf32_rna(v.x); Wh[0] = h0; Wl[0] = tf32_rna(v.x - h0);
                        float h1 = tf32_rna(v.y); Wh[1] = h1; Wl[1] = tf32_rna(v.y - h1);
                        float h2 = tf32_rna(v.z); Wh[2] = h2; Wl[2] = tf32_rna(v.z - h2);
                        float h3 = tf32_rna(v.w); Wh[3] = h3; Wl[3] = tf32_rna(v.w - h3);
                    }
                }
                __syncthreads();
                uint32_t Ah[4], Al[4];
                Ah[0] = fbits(sm[E_H + g * 132 + k2 + tg]);
                Ah[1] = fbits(sm[E_H + (g + 8) * 132 + k2 + tg]);
                Ah[2] = fbits(sm[E_H + g * 132 + k2 + tg + 4]);
                Ah[3] = fbits(sm[E_H + (g + 8) * 132 + k2 + tg + 4]);
                Al[0] = fbits(sm[E_HL + g * 132 + k2 + tg]);
                Al[1] = fbits(sm[E_HL + (g + 8) * 132 + k2 + tg]);
                Al[2] = fbits(sm[E_HL + g * 132 + k2 + tg + 4]);
                Al[3] = fbits(sm[E_HL + (g + 8) * 132 + k2 + tg + 4]);
#pragma unroll
                for (int j = 0; j < 8; j++) {
                    int nrow = warp * 64 + j * 8 + g;
                    uint32_t Bh[2], Bl[2];
                    Bh[0] = fbits(sm[E_W + nrow * 12 + tg]);
                    Bh[1] = fbits(sm[E_W + nrow * 12 + tg + 4]);
                    Bl[0] = fbits(sm[E_W2L + nrow * 12 + tg]);
                    Bl[1] = fbits(sm[E_W2L + nrow * 12 + tg + 4]);
                    mma8(c2[j], Ah, Bh);
                    mma8(c2[j], Ah, Bl);
                    mma8(c2[j], Al, Bh);
                }
            }
        }
        // chunk epilogue: y = wt*(acc + b2) -> per-slot buffer
#pragma unroll
        for (int j = 0; j < 8; j++)
#pragma unroll
            for (int half = 0; half < 2; half++) {
                int row = g + 8 * half;
                if (row < n) {
                    int col = warp * 64 + j * 8 + 2 * tg;
                    int tk = stok[row];
                    float wt = swt[row];
                    float2 bb = __ldg((const float2*)(b2 + (size_t)e * DIM + col));
                    float2 o;
                    o.x = wt * (c2[j][half * 2 + 0] + bb.x);
                    o.y = wt * (c2[j][half * 2 + 1] + bb.y);
                    *(float2*)(g_eo_slot[sslot[row]] + (size_t)tk * DIM + col) = o;
                }
            }
    }
}

// ---------------- K3: micro router (top-8 of 325, exact fp32), materializes eo ----------------
__global__ __launch_bounds__(512) void k_mrouter(const float* __restrict__ mw,
                                                 const float* __restrict__ mb) {
    __shared__ float xs[8 * DIM];
    __shared__ float probs[8][NM + 3];
    int t0 = blockIdx.x * 8;
    int tid = threadIdx.x;
    for (int idx = tid; idx < 8 * (DIM / 4); idx += 512) {
        int c = idx >> 7, q = idx & 127;
        int t = t0 + c;
        float4 a = ((const float4*)g_eo_slot[0])[t * 128 + q];
        float4 b = ((const float4*)g_eo_slot[1])[t * 128 + q];
        float4 v = make_float4(a.x + b.x, a.y + b.y, a.z + b.z, a.w + b.w);
        ((float4*)xs)[idx] = v;
        ((float4*)g_eo)[t * 128 + q] = v;
    }
    __syncthreads();
    for (int m = tid; m < NM; m += 512) {
        float acc[8];
        float bb = __ldg(mb + m);
#pragma unroll
        for (int c = 0; c < 8; c++) acc[c] = bb;
        const float4* wr = (const float4*)(mw + (size_t)m * DIM);
        for (int q = 0; q < DIM / 4; q++) {
            float4 wv = __ldg(wr + q);
#pragma unroll
            for (int c = 0; c < 8; c++) acc[c] += dot4(wv, ((float4*)xs)[c * 128 + q]);
        }
#pragma unroll
        for (int c = 0; c < 8; c++) probs[c][m] = acc[c];
    }
    __syncthreads();
    int w = tid >> 5, lane = tid & 31;
    if (w < 8) {
        float* pr = probs[w];
        float mx = -1e30f;
        for (int i = lane; i < NM; i += 32) mx = fmaxf(mx, pr[i]);
#pragma unroll
        for (int off = 16; off; off >>= 1) mx = fmaxf(mx, __shfl_xor_sync(0xffffffff, mx, off));
        float s = 0.f;
        for (int i = lane; i < NM; i += 32) {
            float p = expf(pr[i] - mx);
            pr[i] = p;
            s += p;
        }
#pragma unroll
        for (int off = 16; off; off >>= 1) s += __shfl_xor_sync(0xffffffff, s, off);
        __syncwarp();
        float vals[TOPM];
        int idxs[TOPM];
#pragma unroll
        for (int k = 0; k < TOPM; k++) {
            float bv = -1e30f;
            int bi = NM;
            for (int i = lane; i < NM; i += 32) {
                float v = pr[i];
                if (v > bv) { bv = v; bi = i; }
            }
#pragma unroll
            for (int off = 16; off; off >>= 1) {
                float ov = __shfl_down_sync(0xffffffff, bv, off);
                int oi = __shfl_down_sync(0xffffffff, bi, off);
                if (ov > bv || (ov == bv && oi < bi)) { bv = ov; bi = oi; }
            }
            bi = __shfl_sync(0xffffffff, bi, 0);
            bv = __shfl_sync(0xffffffff, bv, 0);
            vals[k] = bv;
            idxs[k] = bi;
            if (lane == 0) pr[bi] = -1e30f;
            __syncwarp();
        }
        if (lane == 0) {
            float ssum = 0.f;
#pragma unroll
            for (int k = 0; k < TOPM; k++) ssum += vals[k] / s;
            float den = ssum + 1e-8f;
            int t = t0 + w;
#pragma unroll
            for (int k = 0; k < TOPM; k++) {
                int m = idxs[k];
                float p = (vals[k] / s) / den;
                int pos = atomicAdd(&g_mcount[m], 1);
                g_mlist[m * MCAP + pos] = t | (k << 16);
                g_mwt[m * MCAP + pos] = p;
            }
        }
    }
}

// ---------------- K4: grouped micro FFN (single tf32 mma) + fused layernorm ----------------
#define M_W  0        // Ws 128*36=4608 / W2s 512*20=10240
#define M_X  10240    // 16*36
#define M_H  10816    // 16*132
#define M_TOT 12928   // floats -> 51712 bytes ; rs[16][516]=8256 overlays M_W

__global__ __launch_bounds__(256, 2) void k_mffn(const float* __restrict__ w1,
                                                 const float* __restrict__ b1,
                                                 const float* __restrict__ w2,
                                                 const float* __restrict__ b2,
                                                 const float* __restrict__ gg,
                                                 const float* __restrict__ bbeta) {
    extern __shared__ float sm[];
    __shared__ int stok[MT];
    __shared__ int sslot[MT];
    __shared__ float swt[MT];
    int e = blockIdx.x;
    int cnt = g_mcount[e];
    int tid = threadIdx.x;
    int warp = tid >> 5, lane = tid & 31;
    int g = lane >> 2, tg = lane & 3;
    const float* w1e = w1 + (size_t)e * HID * DIM;
    const float* w2e = w2 + (size_t)e * DIM * HID;

    for (int chunk = blockIdx.y; chunk * MT < cnt; chunk += gridDim.y) {
        int base = chunk * MT;
        int n = min(MT, cnt - base);
        __syncthreads();
        if (tid < MT) {
            if (tid < n) {
                int pk = g_mlist[e * MCAP + base + tid];
                stok[tid] = pk & 0xffff;
                sslot[tid] = pk >> 16;
                swt[tid] = g_mwt[e * MCAP + base + tid];
            } else stok[tid] = -1;
        }
        __syncthreads();

        float c2[8][4];
#pragma unroll
        for (int j = 0; j < 8; j++)
#pragma unroll
            for (int r = 0; r < 4; r++) c2[j][r] = 0.f;

        for (int pass = 0; pass < 2; pass++) {
            int hbase = pass * 128;
            float c1[2][4];
#pragma unroll
            for (int j = 0; j < 2; j++)
#pragma unroll
                for (int r = 0; r < 4; r++) c1[j][r] = 0.f;

            // stage 1: H[16,128] = eo[16,512] @ W1[hbase:+128, :]^T
            for (int k0 = 0; k0 < DIM; k0 += 32) {
                __syncthreads();
                if (tid < 128) {
                    int row = tid >> 3, c4 = (tid & 7) * 4;
                    float4 v = make_float4(0.f, 0.f, 0.f, 0.f);
                    int tk = stok[row];
                    if (tk >= 0) v = ((const float4*)g_eo)[tk * 128 + (k0 + c4) / 4];
                    float* X = sm + M_X + row * 36 + c4;
                    X[0] = tf32_rna(v.x); X[1] = tf32_rna(v.y);
                    X[2] = tf32_rna(v.z); X[3] = tf32_rna(v.w);
                }
                {
                    int c4 = (tid & 7) * 4;
#pragma unroll
                    for (int i = 0; i < 4; i++) {
                        int row = (tid >> 3) + i * 32;
                        float4 v = __ldg((const float4*)(w1e + (size_t)(hbase + row) * DIM + k0 + c4));
                        float* W = sm + M_W + row * 36 + c4;
                        W[0] = tf32_rna(v.x); W[1] = tf32_rna(v.y);
                        W[2] = tf32_rna(v.z); W[3] = tf32_rna(v.w);
                    }
                }
                __syncthreads();
#pragma unroll
                for (int kk = 0; kk < 32; kk += 8) {
                    uint32_t A[4];
                    A[0] = fbits(sm[M_X + g * 36 + kk + tg]);
                    A[1] = fbits(sm[M_X + (g + 8) * 36 + kk + tg]);
                    A[2] = fbits(sm[M_X + g * 36 + kk + tg + 4]);
                    A[3] = fbits(sm[M_X + (g + 8) * 36 + kk + tg + 4]);
#pragma unroll
                    for (int j = 0; j < 2; j++) {
                        int nrow = warp * 16 + j * 8 + g;
                        uint32_t B[2];
                        B[0] = fbits(sm[M_W + nrow * 36 + kk + tg]);
                        B[1] = fbits(sm[M_W + nrow * 36 + kk + tg + 4]);
                        mma8(c1[j], A, B);
                    }
                }
            }
#pragma unroll
            for (int j = 0; j < 2; j++)
#pragma unroll
                for (int r = 0; r < 4; r++) {
                    int row = g + 8 * (r >> 1);
                    int col = warp * 16 + j * 8 + 2 * tg + (r & 1);
                    float v = c1[j][r] + __ldg(b1 + (size_t)e * HID + hbase + col);
                    sm[M_H + row * 132 + col] = tf32_rna(gelu_f(v));
                }

            // stage 2: Y[16,512] += H[16,128] @ W2[:, hbase:+128]^T
            for (int k2 = 0; k2 < 128; k2 += 16) {
                __syncthreads();
                {
                    int c4 = (tid & 3) * 4;
#pragma unroll
                    for (int i = 0; i < 8; i++) {
                        int row = (tid >> 2) + i * 64;
                        float4 v = __ldg((const float4*)(w2e + (size_t)row * HID + hbase + k2 + c4));
                        float* W = sm + M_W + row * 20 + c4;
                        W[0] = tf32_rna(v.x); W[1] = tf32_rna(v.y);
                        W[2] = tf32_rna(v.z); W[3] = tf32_rna(v.w);
                    }
                }
                __syncthreads();
#pragma unroll
                for (int kk = 0; kk < 16; kk += 8) {
                    uint32_t A[4];
                    A[0] = fbits(sm[M_H + g * 132 + k2 + kk + tg]);
                    A[1] = fbits(sm[M_H + (g + 8) * 132 + k2 + kk + tg]);
                    A[2] = fbits(sm[M_H + g * 132 + k2 + kk + tg + 4]);
                    A[3] = fbits(sm[M_H + (g + 8) * 132 + k2 + kk + tg + 4]);
#pragma unroll
                    for (int j = 0; j < 8; j++) {
                        int nrow = warp * 64 + j * 8 + g;
                        uint32_t B[2];
                        B[0] = fbits(sm[M_W + nrow * 20 + kk + tg]);
                        B[1] = fbits(sm[M_W + nrow * 20 + kk + tg + 4]);
                        mma8(c2[j], A, B);
                    }
                }
            }
        }
        // epilogue: rs = eo + ym + b2 (smem), then per-token layernorm
        __syncthreads();
        float* rs = sm;  // 16 x 516, overlays weight staging
#pragma unroll
        for (int j = 0; j < 8; j++)
#pragma unroll
            for (int half = 0; half < 2; half++) {
                int row = g + 8 * half;
                if (row < n) {
                    int col = warp * 64 + j * 8 + 2 * tg;
                    int tk = stok[row];
                    float2 bb = __ldg((const float2*)(b2 + (size_t)e * DIM + col));
                    float2 ev = *(const float2*)(g_eo + (size_t)tk * DIM + col);
                    rs[row * 516 + col] = ev.x + c2[j][half * 2 + 0] + bb.x;
                    rs[row * 516 + col + 1] = ev.y + c2[j][half * 2 + 1] + bb.y;
                }
            }
        __syncthreads();
#pragma unroll
        for (int ci = 0; ci < 2; ci++) {
            int c = warp * 2 + ci;
            if (c < n) {
                float s = 0.f, q = 0.f;
#pragma unroll
                for (int i = 0; i < 16; i++) {
                    float v = rs[c * 516 + lane + i * 32];
                    s += v;
                    q += v * v;
                }
#pragma unroll
                for (int off = 16; off; off >>= 1) {
                    s += __shfl_xor_sync(0xffffffff, s, off);
                    q += __shfl_xor_sync(0xffffffff, q, off);
                }
                float mu = s * (1.0f / DIM);
                float var = q * (1.0f / DIM) - mu * mu;
                float rstd = rsqrtf(var + 1e-5f);
                int t = stok[c];
                float p = swt[c];
                float* dst = g_mo_slot[sslot[c]] + (size_t)t * DIM;
#pragma unroll
                for (int i = 0; i < 16; i++) {
                    int d = lane + i * 32;
                    float nv = (rs[c * 516 + d] - mu) * rstd * __ldg(gg + (size_t)e * DIM + d)
                             + __ldg(bbeta + (size_t)e * DIM + d);
                    dst[d] = p * nv;
                }
            }
        }
    }
}

// ---------------- K5: combine + final layernorm ----------------
__global__ __launch_bounds__(256) void k_final(const float* __restrict__ ng,
                                               const float* __restrict__ nb,
                                               float* __restrict__ out) {
    int t = blockIdx.x;
    int tid = threadIdx.x;
    __shared__ float rsum[8], rsq[8];
    __shared__ float smu, srstd;
    float v[2];
#pragma unroll
    for (int j = 0; j < 2; j++) {
        int d = tid + j * 256;
        float c = g_eo[(size_t)t * DIM + d];
        float mo = 0.f;
#pragma unroll
        for (int k = 0; k < TOPM; k++) mo += g_mo_slot[k][(size_t)t * DIM + d];
        v[j] = c + 0.1f * mo;
    }
    float s = v[0] + v[1];
    float q = v[0] * v[0] + v[1] * v[1];
#pragma unroll
    for (int off = 16; off; off >>= 1) {
        s += __shfl_xor_sync(0xffffffff, s, off);
        q += __shfl_xor_sync(0xffffffff, q, off);
    }
    int w = tid >> 5, lane = tid & 31;
    if (lane == 0) { rsum[w] = s; rsq[w] = q; }
    __syncthreads();
    if (tid == 0) {
        float ts = 0.f, tq = 0.f;
#pragma unroll
        for (int i = 0; i < 8; i++) { ts += rsum[i]; tq += rsq[i]; }
        float mu = ts * (1.0f / DIM);
        float var = tq * (1.0f / DIM) - mu * mu;
        smu = mu;
        srstd = rsqrtf(var + 1e-5f);
    }
    __syncthreads();
    float mu = smu, rstd = srstd;
#pragma unroll
    for (int j = 0; j < 2; j++) {
        int d = tid + j * 256;
        out[(size_t)t * DIM + d] = (v[j] - mu) * rstd * __ldg(ng + d) + __ldg(nb + d);
    }
}

// ---------------- launch ----------------
extern "C" void kernel_launch(void* const* d_in, const int* in_sizes, int n_in,
                              void* d_out, int out_size) {
    const float* x   = (const float*)d_in[0];
    const float* rw  = (const float*)d_in[1];
    const float* rb  = (const float*)d_in[2];
    const float* ew1 = (const float*)d_in[3];
    const float* eb1 = (const float*)d_in[4];
    const float* ew2 = (const float*)d_in[5];
    const float* eb2 = (const float*)d_in[6];
    const float* mrw = (const float*)d_in[7];
    const float* mrb = (const float*)d_in[8];
    const float* mw1 = (const float*)d_in[9];
    const float* mb1 = (const float*)d_in[10];
    const float* mw2 = (const float*)d_in[11];
    const float* mb2 = (const float*)d_in[12];
    const float* mg  = (const float*)d_in[13];
    const float* mbt = (const float*)d_in[14];
    const float* ng  = (const float*)d_in[15];
    const float* nb  = (const float*)d_in[16];
    float* out = (float*)d_out;

    cudaFuncSetAttribute(k_effn, cudaFuncAttributeMaxDynamicSharedMemorySize, E_TOT * 4);
    cudaFuncSetAttribute(k_mffn, cudaFuncAttributeMaxDynamicSharedMemorySize, M_TOT * 4);

    k_zero<<<1, 512>>>();
    k_erouter<<<T / 256, 256>>>(x, rw, rb);
    k_effn<<<dim3(NE, 16), 256, E_TOT * 4>>>(x, ew1, eb1, ew2, eb2);
    k_mrouter<<<T / 8, 512>>>(mrw, mrb);
    k_mffn<<<dim3(NM, 2), 256, M_TOT * 4>>>(mw1, mb1, mw2, mb2, mg, mbt);
    k_final<<<T, 256>>>(ng, nb, out);
}